// round 1
// baseline (speedup 1.0000x reference)
#include <cuda_runtime.h>
#include <cuda_bf16.h>

// Problem constants (shapes are fixed by the dataset).
#define MAXN   50000
#define INC    128
#define OUTC   64
#define BN_EPS 1e-5f

// ---------------- scratch (device globals; no allocations allowed) ----------
__device__ float g_h[MAXN * OUTC];     // h = x @ W
__device__ float g_agg[MAXN * OUTC];   // aggregation accumulator, then tanh output (in place)
__device__ int   g_deg[MAXN];          // in-degree incl. self loop
__device__ float g_dinv[MAXN];         // deg^{-1/2}
__device__ float g_sum[OUTC];          // BN channel sums
__device__ float g_sqsum[OUTC];        // BN channel sum of squares
__device__ int   g_is64;               // edge_index dtype flag (1 = int64)

// ---------------- kernel 1: init + dtype detect -----------------------------
// deg[i] = 1 (self loop), zero BN sums, detect int64-vs-int32 edge buffer.
__global__ void k_init(const int* __restrict__ ei32, int E, int n) {
    int i = blockIdx.x * blockDim.x + threadIdx.x;
    if (i < n) g_deg[i] = 1;
    if (blockIdx.x == 0) {
        __shared__ int flag;
        if (threadIdx.x == 0) flag = 0;
        __syncthreads();
        int checks = min(256, E);
        if ((int)threadIdx.x < checks) {
            // If data is int64, every odd 32-bit word is a high word == 0
            // (indices are in [0, 50000)). If int32 these are random indices.
            if (ei32[2 * threadIdx.x + 1] != 0) atomicOr(&flag, 1);
        }
        __syncthreads();
        if (threadIdx.x == 0) g_is64 = (flag == 0) ? 1 : 0;
        if (threadIdx.x < OUTC) { g_sum[threadIdx.x] = 0.f; g_sqsum[threadIdx.x] = 0.f; }
    }
}

// ---------------- kernel 2: degree ------------------------------------------
__global__ void k_deg(const int* __restrict__ ei, int E) {
    int e = blockIdx.x * blockDim.x + threadIdx.x;
    if (e >= E) return;
    int dst = g_is64 ? ei[2 * (E + e)] : ei[E + e];
    atomicAdd(&g_deg[dst], 1);
}

// ---------------- kernel 3: dinv --------------------------------------------
__global__ void k_dinv(int n) {
    int i = blockIdx.x * blockDim.x + threadIdx.x;
    if (i < n) g_dinv[i] = rsqrtf((float)g_deg[i]);   // deg >= 1 always
}

// ---------------- kernel 4: GEMM h = x @ W, and agg init = h * dinv^2 -------
// 32 rows per block, 128 threads, each thread computes a 4x4 register tile.
__global__ __launch_bounds__(128) void k_gemm(const float* __restrict__ x,
                                              const float* __restrict__ W,
                                              int n) {
    __shared__ float xs[32 * INC];     // 16 KB
    __shared__ float ws[INC * OUTC];   // 32 KB
    const int tid  = threadIdx.x;
    const int row0 = blockIdx.x * 32;

    // load W (8192 floats = 2048 float4; 16 per thread)
    {
        const float4* W4  = reinterpret_cast<const float4*>(W);
        float4*       ws4 = reinterpret_cast<float4*>(ws);
        #pragma unroll
        for (int i = 0; i < 16; i++) ws4[tid + i * 128] = W4[tid + i * 128];
    }
    // load x tile (4096 floats = 1024 float4; 8 per thread), zero-pad tail rows
    {
        const float4* x4  = reinterpret_cast<const float4*>(x);
        float4*       xs4 = reinterpret_cast<float4*>(xs);
        #pragma unroll
        for (int i = 0; i < 8; i++) {
            int idx = tid + i * 128;          // float4 index inside tile (32 per row)
            int r   = row0 + (idx >> 5);
            float4 v = make_float4(0.f, 0.f, 0.f, 0.f);
            if (r < n) v = x4[(size_t)r * 32 + (idx & 31)];
            xs4[idx] = v;
        }
    }
    __syncthreads();

    const int tx = tid & 15;   // column group (4 cols)
    const int ty = tid >> 4;   // row group (4 rows)
    float acc[4][4];
    #pragma unroll
    for (int i = 0; i < 4; i++)
        #pragma unroll
        for (int j = 0; j < 4; j++) acc[i][j] = 0.f;

    const float4* wsv = reinterpret_cast<const float4*>(ws);
    #pragma unroll 8
    for (int k = 0; k < INC; k++) {
        float4 w = wsv[k * 16 + tx];
        #pragma unroll
        for (int i = 0; i < 4; i++) {
            float xv = xs[(ty * 4 + i) * INC + k];
            acc[i][0] += xv * w.x;
            acc[i][1] += xv * w.y;
            acc[i][2] += xv * w.z;
            acc[i][3] += xv * w.w;
        }
    }

    #pragma unroll
    for (int i = 0; i < 4; i++) {
        int r = row0 + ty * 4 + i;
        if (r < n) {
            float di = g_dinv[r];
            float d2 = di * di;
            float4 hv = make_float4(acc[i][0], acc[i][1], acc[i][2], acc[i][3]);
            reinterpret_cast<float4*>(g_h)[r * 16 + tx] = hv;
            float4 av = make_float4(hv.x * d2, hv.y * d2, hv.z * d2, hv.w * d2);
            reinterpret_cast<float4*>(g_agg)[r * 16 + tx] = av;
        }
    }
}

// ---------------- kernel 5: edge scatter -------------------------------------
// 16 threads per edge; each thread handles one float4 (4 channels) and issues
// a single vector reduction (red.global.add.v4.f32).
__global__ __launch_bounds__(256) void k_edges(const int* __restrict__ ei, int E) {
    int t = blockIdx.x * blockDim.x + threadIdx.x;
    int e = t >> 4;
    if (e >= E) return;
    unsigned mask = __activemask();     // whole 16-groups exit together
    int lane = threadIdx.x & 31;
    int sub  = lane & 15;

    int s = 0, d = 0;
    float nrm = 0.f;
    if (sub == 0) {
        if (g_is64) { s = ei[2 * e]; d = ei[2 * (E + e)]; }
        else        { s = ei[e];     d = ei[E + e]; }
        nrm = g_dinv[s] * g_dinv[d];
    }
    int srcl = lane & 16;               // group leader lane (0 or 16)
    s   = __shfl_sync(mask, s, srcl);
    d   = __shfl_sync(mask, d, srcl);
    nrm = __shfl_sync(mask, nrm, srcl);

    float4 v = reinterpret_cast<const float4*>(g_h)[s * 16 + sub];
    float4* dst = reinterpret_cast<float4*>(g_agg) + d * 16 + sub;
    asm volatile("red.global.add.v4.f32 [%0], {%1, %2, %3, %4};"
                 :: "l"(dst), "f"(v.x * nrm), "f"(v.y * nrm),
                    "f"(v.z * nrm), "f"(v.w * nrm)
                 : "memory");
}

// ---------------- kernel 6: bias + tanh (in place) + BN partial stats --------
__global__ __launch_bounds__(256) void k_tanh_stats(const float* __restrict__ bias, int n) {
    const int total  = n * OUTC;
    const int stride = gridDim.x * blockDim.x;     // multiple of 64
    const int c      = threadIdx.x & 63;           // channel fixed per thread
    const float b    = bias[c];
    float s = 0.f, s2 = 0.f;
    for (int i = blockIdx.x * blockDim.x + threadIdx.x; i < total; i += stride) {
        float a = tanhf(g_agg[i] + b);
        g_agg[i] = a;
        s  += a;
        s2 += a * a;
    }
    __shared__ float sh[256], sh2[256];
    sh[threadIdx.x]  = s;
    sh2[threadIdx.x] = s2;
    __syncthreads();
    if (threadIdx.x < 64) {
        float t  = sh[threadIdx.x]  + sh[threadIdx.x + 64]  + sh[threadIdx.x + 128]  + sh[threadIdx.x + 192];
        float t2 = sh2[threadIdx.x] + sh2[threadIdx.x + 64] + sh2[threadIdx.x + 128] + sh2[threadIdx.x + 192];
        atomicAdd(&g_sum[c],   t);
        atomicAdd(&g_sqsum[c], t2);
    }
}

// ---------------- kernel 7: BN normalize -------------------------------------
__global__ __launch_bounds__(256) void k_norm(const float* __restrict__ gamma,
                                              const float* __restrict__ beta,
                                              float* __restrict__ out, int n) {
    const int total  = n * OUTC;
    const int stride = gridDim.x * blockDim.x;     // multiple of 64
    const int c      = threadIdx.x & 63;
    const float inv_n = 1.f / (float)n;
    float mean  = g_sum[c]   * inv_n;
    float var   = g_sqsum[c] * inv_n - mean * mean;
    float scale = gamma[c] * rsqrtf(var + BN_EPS);
    float shift = beta[c] - mean * scale;
    for (int i = blockIdx.x * blockDim.x + threadIdx.x; i < total; i += stride) {
        out[i] = g_agg[i] * scale + shift;
    }
}

// ---------------- launch -----------------------------------------------------
extern "C" void kernel_launch(void* const* d_in, const int* in_sizes, int n_in,
                              void* d_out, int out_size) {
    const float* x     = (const float*)d_in[0];
    const int*   ei    = (const int*)d_in[1];    // int32 view; dtype detected on device
    const float* W     = (const float*)d_in[2];
    const float* bias  = (const float*)d_in[3];
    const float* gamma = (const float*)d_in[4];
    const float* beta  = (const float*)d_in[5];
    float* out = (float*)d_out;

    const int n = in_sizes[0] / INC;             // 50000
    const int E = in_sizes[1] / 2;               // 800000 (same for int32/int64 views)

    const int nblk = (n + 255) / 256;
    k_init<<<nblk, 256>>>(ei, E, n);
    k_deg<<<(E + 255) / 256, 256>>>(ei, E);
    k_dinv<<<nblk, 256>>>(n);
    k_gemm<<<(n + 31) / 32, 128>>>(x, W, n);
    {
        long long tthreads = (long long)E * 16;
        int gblk = (int)((tthreads + 255) / 256);
        k_edges<<<gblk, 256>>>(ei, E);
    }
    k_tanh_stats<<<256, 256>>>(bias, n);
    k_norm<<<256, 256>>>(gamma, beta, out, n);
}

// round 2
// speedup vs baseline: 1.1239x; 1.1239x over previous
#include <cuda_runtime.h>
#include <cuda_bf16.h>

// Problem constants (shapes fixed by the dataset).
#define MAXN   50000
#define INC    128
#define OUTC   64
#define BN_EPS 1e-5f

// ---------------- scratch (device globals; no allocations allowed) ----------
__device__ float g_h[MAXN * OUTC];     // h = x @ W
__device__ float g_agg[MAXN * OUTC];   // aggregation accumulator, then tanh output (in place)
__device__ int   g_deg[MAXN];          // in-degree incl. self loop
__device__ float g_dinv[MAXN];         // deg^{-1/2}
__device__ float g_sum[OUTC];          // BN channel sums
__device__ float g_sqsum[OUTC];        // BN channel sum of squares
__device__ int   g_is64;               // edge_index dtype flag (1 = int64)

// ---------------- f32x2 packed-math helpers ---------------------------------
__device__ __forceinline__ unsigned long long pk2(float a, float b) {
    unsigned long long r;
    asm("mov.b64 %0, {%1, %2};" : "=l"(r) : "f"(a), "f"(b));
    return r;
}
__device__ __forceinline__ void fma2(unsigned long long& d,
                                     unsigned long long a,
                                     unsigned long long b) {
    asm("fma.rn.f32x2 %0, %1, %2, %0;" : "+l"(d) : "l"(a), "l"(b));
}
__device__ __forceinline__ float2 up2(unsigned long long v) {
    float2 f;
    asm("mov.b64 {%0, %1}, %2;" : "=f"(f.x), "=f"(f.y) : "l"(v));
    return f;
}

// ---------------- kernel 1: init + dtype detect -----------------------------
__global__ void k_init(const int* __restrict__ ei32, int E, int n) {
    int i = blockIdx.x * blockDim.x + threadIdx.x;
    if (i < n) g_deg[i] = 1;
    if (blockIdx.x == 0) {
        __shared__ int flag;
        if (threadIdx.x == 0) flag = 0;
        __syncthreads();
        int checks = min(256, E);
        if ((int)threadIdx.x < checks) {
            // int64 data => every odd 32-bit word is a zero high word
            // (indices are < 50000). int32 => these are random indices.
            if (ei32[2 * threadIdx.x + 1] != 0) atomicOr(&flag, 1);
        }
        __syncthreads();
        if (threadIdx.x == 0) g_is64 = (flag == 0) ? 1 : 0;
        if (threadIdx.x < OUTC) { g_sum[threadIdx.x] = 0.f; g_sqsum[threadIdx.x] = 0.f; }
    }
}

// ---------------- kernel 2: degree ------------------------------------------
__global__ void k_deg(const int* __restrict__ ei, int E) {
    int e = blockIdx.x * blockDim.x + threadIdx.x;
    if (e >= E) return;
    int dst = g_is64 ? ei[2 * (E + e)] : ei[E + e];
    atomicAdd(&g_deg[dst], 1);
}

// ---------------- kernel 3: dinv --------------------------------------------
__global__ void k_dinv(int n) {
    int i = blockIdx.x * blockDim.x + threadIdx.x;
    if (i < n) g_dinv[i] = rsqrtf((float)g_deg[i]);   // deg >= 1 always
}

// ---------------- kernel 4: GEMM h = x @ W (f32x2), agg init = h * dinv^2 ---
// 128 threads, block tile 128 rows x 64 cols, K chunked by 32.
// Thread tile: 8 rows x 8 cols as 8x4 f32x2 (column-pair) accumulators.
// xs row-major with stride 33 floats: conflict-free for both the scalar STS
// fill (bank = (row + 4*kf4 + j) mod 32, all distinct in a warp) and the
// mainloop broadcast reads (bank = (8*rowg + i + k) mod 32).
#define BK 32
#define XS_STRIDE 33
__global__ __launch_bounds__(128) void k_gemm(const float* __restrict__ x,
                                              const float* __restrict__ W,
                                              int n) {
    __shared__ float xs[128 * XS_STRIDE];   // 16896 B
    __shared__ float ws[BK * OUTC];         //  8192 B

    const int tid  = threadIdx.x;
    const int row0 = blockIdx.x * 128;
    const int colg = tid & 7;               // 8 cols each: colg*8 .. colg*8+7
    const int rowg = tid >> 3;              // 16 groups of 8 rows

    unsigned long long acc[8][4];
    #pragma unroll
    for (int r = 0; r < 8; r++)
        #pragma unroll
        for (int c = 0; c < 4; c++) acc[r][c] = 0ull;

    const float4* x4 = reinterpret_cast<const float4*>(x);
    const float4* W4 = reinterpret_cast<const float4*>(W);
    float4*       ws4 = reinterpret_cast<float4*>(ws);
    const float4* wsr = reinterpret_cast<const float4*>(ws);

    for (int kc = 0; kc < INC / BK; kc++) {
        // --- load x chunk: 128 rows x 32 k, row-major stride 33, scalar STS
        {
            const int lrow = tid >> 3;      // 0..15 (+16 per pass)
            const int kf4  = tid & 7;       // float4 index within chunk
            #pragma unroll
            for (int p = 0; p < 8; p++) {
                int r  = lrow + p * 16;
                int gr = row0 + r;
                float4 v = make_float4(0.f, 0.f, 0.f, 0.f);
                if (gr < n) v = x4[(size_t)gr * (INC / 4) + kc * 8 + kf4];
                float* dstp = &xs[r * XS_STRIDE + kf4 * 4];
                dstp[0] = v.x; dstp[1] = v.y; dstp[2] = v.z; dstp[3] = v.w;
            }
        }
        // --- load W chunk: 32 k x 64 cols = 512 float4, 4 per thread
        {
            #pragma unroll
            for (int i = 0; i < 4; i++)
                ws4[tid + i * 128] = W4[kc * (BK * OUTC / 4) + tid + i * 128];
        }
        __syncthreads();

        #pragma unroll 4
        for (int k = 0; k < BK; k++) {
            float4 wa = wsr[k * 16 + colg * 2];
            float4 wb = wsr[k * 16 + colg * 2 + 1];
            unsigned long long wp0 = pk2(wa.x, wa.y);
            unsigned long long wp1 = pk2(wa.z, wa.w);
            unsigned long long wp2 = pk2(wb.x, wb.y);
            unsigned long long wp3 = pk2(wb.z, wb.w);
            #pragma unroll
            for (int r = 0; r < 8; r++) {
                float xv = xs[(rowg * 8 + r) * XS_STRIDE + k];
                unsigned long long xp = pk2(xv, xv);
                fma2(acc[r][0], xp, wp0);
                fma2(acc[r][1], xp, wp1);
                fma2(acc[r][2], xp, wp2);
                fma2(acc[r][3], xp, wp3);
            }
        }
        __syncthreads();
    }

    // --- epilogue: write h and agg = h * dinv^2 (self-loop term)
    #pragma unroll
    for (int r = 0; r < 8; r++) {
        int gr = row0 + rowg * 8 + r;
        if (gr < n) {
            float di = g_dinv[gr];
            float d2 = di * di;
            float2 a0 = up2(acc[r][0]);
            float2 a1 = up2(acc[r][1]);
            float2 a2 = up2(acc[r][2]);
            float2 a3 = up2(acc[r][3]);
            float4 h0 = make_float4(a0.x, a0.y, a1.x, a1.y);
            float4 h1 = make_float4(a2.x, a2.y, a3.x, a3.y);
            float4* hp = reinterpret_cast<float4*>(g_h)  + (size_t)gr * 16 + colg * 2;
            float4* ap = reinterpret_cast<float4*>(g_agg) + (size_t)gr * 16 + colg * 2;
            hp[0] = h0;
            hp[1] = h1;
            ap[0] = make_float4(h0.x * d2, h0.y * d2, h0.z * d2, h0.w * d2);
            ap[1] = make_float4(h1.x * d2, h1.y * d2, h1.z * d2, h1.w * d2);
        }
    }
}

// ---------------- kernel 5: edge scatter -------------------------------------
// 16 threads per edge; each thread handles one float4 (4 channels) and issues
// a single vector reduction (red.global.add.v4.f32).
__global__ __launch_bounds__(256) void k_edges(const int* __restrict__ ei, int E) {
    int t = blockIdx.x * blockDim.x + threadIdx.x;
    int e = t >> 4;
    if (e >= E) return;
    unsigned mask = __activemask();     // whole 16-groups exit together
    int lane = threadIdx.x & 31;
    int sub  = lane & 15;

    int s = 0, d = 0;
    float nrm = 0.f;
    if (sub == 0) {
        if (g_is64) { s = ei[2 * e]; d = ei[2 * (E + e)]; }
        else        { s = ei[e];     d = ei[E + e]; }
        nrm = g_dinv[s] * g_dinv[d];
    }
    int srcl = lane & 16;               // group leader lane (0 or 16)
    s   = __shfl_sync(mask, s, srcl);
    d   = __shfl_sync(mask, d, srcl);
    nrm = __shfl_sync(mask, nrm, srcl);

    float4 v = __ldg(reinterpret_cast<const float4*>(g_h) + (size_t)s * 16 + sub);
    float4* dst = reinterpret_cast<float4*>(g_agg) + (size_t)d * 16 + sub;
    asm volatile("red.global.add.v4.f32 [%0], {%1, %2, %3, %4};"
                 :: "l"(dst), "f"(v.x * nrm), "f"(v.y * nrm),
                    "f"(v.z * nrm), "f"(v.w * nrm)
                 : "memory");
}

// ---------------- kernel 6: bias + tanh (in place) + BN partial stats --------
__global__ __launch_bounds__(256) void k_tanh_stats(const float* __restrict__ bias, int n) {
    const int total  = n * OUTC;
    const int stride = gridDim.x * blockDim.x;     // multiple of 64
    const int c      = threadIdx.x & 63;           // channel fixed per thread
    const float b    = bias[c];
    float s = 0.f, s2 = 0.f;
    for (int i = blockIdx.x * blockDim.x + threadIdx.x; i < total; i += stride) {
        float a = tanhf(g_agg[i] + b);
        g_agg[i] = a;
        s  += a;
        s2 += a * a;
    }
    __shared__ float sh[256], sh2[256];
    sh[threadIdx.x]  = s;
    sh2[threadIdx.x] = s2;
    __syncthreads();
    if (threadIdx.x < 64) {
        float t  = sh[threadIdx.x]  + sh[threadIdx.x + 64]  + sh[threadIdx.x + 128]  + sh[threadIdx.x + 192];
        float t2 = sh2[threadIdx.x] + sh2[threadIdx.x + 64] + sh2[threadIdx.x + 128] + sh2[threadIdx.x + 192];
        atomicAdd(&g_sum[c],   t);
        atomicAdd(&g_sqsum[c], t2);
    }
}

// ---------------- kernel 7: BN normalize -------------------------------------
__global__ __launch_bounds__(256) void k_norm(const float* __restrict__ gamma,
                                              const float* __restrict__ beta,
                                              float* __restrict__ out, int n) {
    const int total  = n * OUTC;
    const int stride = gridDim.x * blockDim.x;     // multiple of 64
    const int c      = threadIdx.x & 63;
    const float inv_n = 1.f / (float)n;
    float mean  = g_sum[c]   * inv_n;
    float var   = g_sqsum[c] * inv_n - mean * mean;
    float scale = gamma[c] * rsqrtf(var + BN_EPS);
    float shift = beta[c] - mean * scale;
    for (int i = blockIdx.x * blockDim.x + threadIdx.x; i < total; i += stride) {
        out[i] = g_agg[i] * scale + shift;
    }
}

// ---------------- launch -----------------------------------------------------
extern "C" void kernel_launch(void* const* d_in, const int* in_sizes, int n_in,
                              void* d_out, int out_size) {
    const float* x     = (const float*)d_in[0];
    const int*   ei    = (const int*)d_in[1];    // int32 view; dtype detected on device
    const float* W     = (const float*)d_in[2];
    const float* bias  = (const float*)d_in[3];
    const float* gamma = (const float*)d_in[4];
    const float* beta  = (const float*)d_in[5];
    float* out = (float*)d_out;

    const int n = in_sizes[0] / INC;             // 50000
    const int E = in_sizes[1] / 2;               // 800000 (same count for int32/int64 views)

    const int nblk = (n + 255) / 256;
    k_init<<<nblk, 256>>>(ei, E, n);
    k_deg<<<(E + 255) / 256, 256>>>(ei, E);
    k_dinv<<<nblk, 256>>>(n);
    k_gemm<<<(n + 127) / 128, 128>>>(x, W, n);
    {
        long long tthreads = (long long)E * 16;
        int gblk = (int)((tthreads + 255) / 256);
        k_edges<<<gblk, 256>>>(ei, E);
    }
    k_tanh_stats<<<256, 256>>>(bias, n);
    k_norm<<<256, 256>>>(gamma, beta, out, n);
}